// round 13
// baseline (speedup 1.0000x reference)
#include <cuda_runtime.h>
#include <cuda.h>
#include <stdint.h>

// ───────────────────────── padded coordinate table ─────────────────────────
// 32B per atom row (8 floats, xyz in the first 3). One TMA gather4 row or one
// fallback LDG touches exactly one 32B L2 sector.
#define MAX_ATOMS 100352
__device__ __align__(1024) float g_R8[MAX_ATOMS][8];

__global__ void pad_R_kernel(const float* __restrict__ R, int n_atoms) {
    int i = blockIdx.x * blockDim.x + threadIdx.x;
    if (i < n_atoms) {
        float4* row = reinterpret_cast<float4*>(g_R8[i]);
        row[0] = make_float4(R[3 * i + 0], R[3 * i + 1], R[3 * i + 2], 0.0f);
    }
}

// ───────────────────────── TMA gather4 kernel ─────────────────────────
#define TILE_EDGES 512
#define TPB 256
#define BLOCK_BYTES 128                      // one gather4 = 4 rows x 32B
#define SIDE_BYTES (TILE_EDGES * 32)         // 16384 per side
#define TX_BYTES (2 * SIDE_BYTES)            // 32768 per tile

__device__ __forceinline__ uint32_t smem_u32(const void* p) {
    uint32_t a;
    asm("{ .reg .u64 t; cvta.to.shared.u64 t, %1; cvt.u32.u64 %0, t; }"
        : "=r"(a) : "l"(p));
    return a;
}

__global__ void __launch_bounds__(TPB)
dist_tma_kernel(const __grid_constant__ CUtensorMap tmap,
                const int* __restrict__ idx_i,
                const int* __restrict__ idx_j,
                float* __restrict__ out,
                int n_edges) {
    __shared__ __align__(8) unsigned long long mbar;
    __shared__ __align__(128) float smemI[SIDE_BYTES / 4];
    __shared__ __align__(128) float smemJ[SIDE_BYTES / 4];

    int t = threadIdx.x;
    unsigned base = blockIdx.x * TILE_EDGES;
    unsigned n = (unsigned)n_edges;
    uint32_t mbar_addr = smem_u32(&mbar);

    if (t == 0) {
        asm volatile("mbarrier.init.shared.b64 [%0], 1;" :: "r"(mbar_addr) : "memory");
        asm volatile("mbarrier.arrive.expect_tx.shared.b64 _, [%0], %1;"
                     :: "r"(mbar_addr), "r"((uint32_t)TX_BYTES) : "memory");
    }
    __syncthreads();

    // Every thread issues exactly one gather4 (256 total = TX_BYTES).
    // t < 128: i-side edges [4k, 4k+4);  t >= 128: j-side.
    {
        int k = t & 127;
        const int* src = (t < 128) ? idx_i : idx_j;
        unsigned e0 = base + 4u * k;
        int4 v;
        if (e0 + 4u <= n) {
            v = *reinterpret_cast<const int4*>(src + e0);
        } else {
            v.x = (e0 + 0u < n) ? src[e0 + 0u] : 0;
            v.y = (e0 + 1u < n) ? src[e0 + 1u] : 0;
            v.z = (e0 + 2u < n) ? src[e0 + 2u] : 0;
            v.w = (e0 + 3u < n) ? src[e0 + 3u] : 0;
        }
        uint32_t dst = ((t < 128) ? smem_u32(smemI) : smem_u32(smemJ))
                       + (uint32_t)k * BLOCK_BYTES;
        asm volatile(
            "cp.async.bulk.tensor.2d.shared::cta.global.tile::gather4"
            ".mbarrier::complete_tx::bytes "
            "[%0], [%1, {%2, %3, %4, %5, %6}], [%7];"
            :: "r"(dst), "l"(&tmap),
               "r"(0), "r"(v.x), "r"(v.y), "r"(v.z), "r"(v.w),
               "r"(mbar_addr)
            : "memory");
    }

    // Wait for all 256 gather4 completions (tx count reaches TX_BYTES).
    {
        uint32_t done;
        asm volatile(
            "{ .reg .pred p; mbarrier.try_wait.parity.acquire.cta.shared::cta.b64 "
            "p, [%1], %2, 0x989680; selp.b32 %0, 1, 0, p; }"
            : "=r"(done) : "r"(mbar_addr), "r"(0u) : "memory");
        while (!done) {
            asm volatile(
                "{ .reg .pred p; mbarrier.try_wait.parity.acquire.cta.shared::cta.b64 "
                "p, [%1], %2, 0x989680; selp.b32 %0, 1, 0, p; }"
                : "=r"(done) : "r"(mbar_addr), "r"(0u) : "memory");
        }
    }

    // Gather4 block g holds rows for edges [4g, 4g+4) contiguously:
    // edge e's row is at byte offset e*32 → float offset e*8.
    #pragma unroll
    for (int s = 0; s < 2; ++s) {
        int e = t + s * TPB;
        unsigned ge = base + (unsigned)e;
        if (ge < n) {
            float4 a = *reinterpret_cast<const float4*>(&smemI[e * 8]);
            float4 b = *reinterpret_cast<const float4*>(&smemJ[e * 8]);
            float dx = a.x - b.x;
            float dy = a.y - b.y;
            float dz = a.z - b.z;
            out[ge] = sqrtf(dx * dx + dy * dy + dz * dz);
        }
    }
}

// ───────────────────────── fallback LDG kernel (proven ~55us) ─────────────────────────
__device__ __forceinline__ int4 ld_stream_int4(const int4* p) {
    int4 v;
    asm volatile("ld.global.nc.L1::no_allocate.v4.b32 {%0,%1,%2,%3}, [%4];"
                 : "=r"(v.x), "=r"(v.y), "=r"(v.z), "=r"(v.w) : "l"(p));
    return v;
}
__device__ __forceinline__ void st_stream_float4(float4* p, float4 v) {
    asm volatile("st.global.cs.v4.f32 [%0], {%1,%2,%3,%4};"
                 :: "l"(p), "f"(v.x), "f"(v.y), "f"(v.z), "f"(v.w) : "memory");
}
__device__ __forceinline__ float edge_dist(int i, int j) {
    float4 a = *reinterpret_cast<const float4*>(g_R8[i]);
    float4 b = *reinterpret_cast<const float4*>(g_R8[j]);
    float dx = a.x - b.x, dy = a.y - b.y, dz = a.z - b.z;
    return sqrtf(dx * dx + dy * dy + dz * dz);
}
__global__ void dist_kernel(const int* __restrict__ idx_i,
                            const int* __restrict__ idx_j,
                            float* __restrict__ out, int n_edges) {
    unsigned t = blockIdx.x * blockDim.x + threadIdx.x;
    unsigned base = t * 8u;
    if (base + 8u <= (unsigned)n_edges) {
        const int4* pi = reinterpret_cast<const int4*>(idx_i + base);
        const int4* pj = reinterpret_cast<const int4*>(idx_j + base);
        int4 i0 = ld_stream_int4(pi + 0);
        int4 i1 = ld_stream_int4(pi + 1);
        int4 j0 = ld_stream_int4(pj + 0);
        int4 j1 = ld_stream_int4(pj + 1);
        float4 r0, r1;
        r0.x = edge_dist(i0.x, j0.x); r0.y = edge_dist(i0.y, j0.y);
        r0.z = edge_dist(i0.z, j0.z); r0.w = edge_dist(i0.w, j0.w);
        r1.x = edge_dist(i1.x, j1.x); r1.y = edge_dist(i1.y, j1.y);
        r1.z = edge_dist(i1.z, j1.z); r1.w = edge_dist(i1.w, j1.w);
        st_stream_float4(reinterpret_cast<float4*>(out + base) + 0, r0);
        st_stream_float4(reinterpret_cast<float4*>(out + base) + 1, r1);
    } else if (base < (unsigned)n_edges) {
        for (unsigned e = base; e < (unsigned)n_edges; ++e)
            out[e] = edge_dist(idx_i[e], idx_j[e]);
    }
}

// ───────────────────────── host ─────────────────────────
typedef CUresult (*PFN_encodeTiled)(
    CUtensorMap*, CUtensorMapDataType, cuuint32_t, void*,
    const cuuint64_t*, const cuuint64_t*, const cuuint32_t*, const cuuint32_t*,
    CUtensorMapInterleave, CUtensorMapSwizzle, CUtensorMapL2promotion,
    CUtensorMapFloatOOBfill);

extern "C" void kernel_launch(void* const* d_in, const int* in_sizes, int n_in,
                              void* d_out, int out_size) {
    const float* R   = (const float*)d_in[0];
    const int* idx_i = (const int*)d_in[1];
    const int* idx_j = (const int*)d_in[2];
    float* out       = (float*)d_out;

    int n_atoms = in_sizes[0] / 3;
    int n_edges = in_sizes[1];

    {
        int threads = 256;
        int blocks = (n_atoms + threads - 1) / threads;
        pad_R_kernel<<<blocks, threads>>>(R, n_atoms);
    }

    // Build gather tensormap host-side. gather4 supplies the 4 row coords in
    // the instruction, so the box is {row_width=8 f32, 1}. If encode fails,
    // fall back to the proven LDG kernel (bounded downside).
    bool use_tma = false;
    CUtensorMap tmap;
    void* fn = nullptr;
    cudaDriverEntryPointQueryResult qres;
    if (cudaGetDriverEntryPoint("cuTensorMapEncodeTiled", &fn,
                                cudaEnableDefault, &qres) == cudaSuccess && fn) {
        void* dR8 = nullptr;
        if (cudaGetSymbolAddress(&dR8, g_R8) == cudaSuccess && dR8) {
            cuuint64_t gdims[2]   = {8, (cuuint64_t)MAX_ATOMS};  // 8 f32 per row
            cuuint64_t gstride[1] = {32};                        // 32B row stride
            cuuint32_t estr[2]    = {1, 1};
            cuuint32_t box[2]     = {8, 1};                      // gather4: height 1
            PFN_encodeTiled enc = (PFN_encodeTiled)fn;
            if (enc(&tmap, CU_TENSOR_MAP_DATA_TYPE_FLOAT32, 2, dR8,
                    gdims, gstride, box, estr,
                    CU_TENSOR_MAP_INTERLEAVE_NONE, CU_TENSOR_MAP_SWIZZLE_NONE,
                    CU_TENSOR_MAP_L2_PROMOTION_NONE,
                    CU_TENSOR_MAP_FLOAT_OOB_FILL_NONE) == CUDA_SUCCESS) {
                use_tma = true;
            }
        }
    }

    if (use_tma) {
        int blocks = (n_edges + TILE_EDGES - 1) / TILE_EDGES;
        dist_tma_kernel<<<blocks, TPB>>>(tmap, idx_i, idx_j, out, n_edges);
    } else {
        int threads = 256;
        int epb = threads * 8;
        int blocks = (n_edges + epb - 1) / epb;
        dist_kernel<<<blocks, threads>>>(idx_i, idx_j, out, n_edges);
    }
}

// round 14
// speedup vs baseline: 1.0125x; 1.0125x over previous
#include <cuda_runtime.h>
#include <cuda.h>
#include <stdint.h>

// ───────────────────────── padded coordinate table ─────────────────────────
// 32B per atom row (8 floats, xyz in the first 3). One TMA gather4 row or one
// fallback LDG touches exactly one 32B L2 sector.
#define MAX_ATOMS 100352
__device__ __align__(1024) float g_R8[MAX_ATOMS][8];

__global__ void pad_R_kernel(const float* __restrict__ R, int n_atoms) {
    int i = blockIdx.x * blockDim.x + threadIdx.x;
    if (i < n_atoms) {
        float4* row = reinterpret_cast<float4*>(g_R8[i]);
        row[0] = make_float4(R[3 * i + 0], R[3 * i + 1], R[3 * i + 2], 0.0f);
    }
}

// ───────────────────────── TMA gather4 kernel ─────────────────────────
#define TILE_EDGES 512
#define TPB 256
#define BLOCK_BYTES 128                      // one gather4 = 4 rows x 32B
#define SIDE_BYTES (TILE_EDGES * 32)         // 16384 per side
#define TX_BYTES (2 * SIDE_BYTES)            // 32768 per tile

__device__ __forceinline__ uint32_t smem_u32(const void* p) {
    uint32_t a;
    asm("{ .reg .u64 t; cvta.to.shared.u64 t, %1; cvt.u32.u64 %0, t; }"
        : "=r"(a) : "l"(p));
    return a;
}

__device__ __forceinline__ void tma_gather4(uint32_t dst, const CUtensorMap* tmap,
                                            int4 rows, uint32_t mbar_addr) {
    asm volatile(
        "cp.async.bulk.tensor.2d.shared::cta.global.tile::gather4"
        ".mbarrier::complete_tx::bytes "
        "[%0], [%1, {%2, %3, %4, %5, %6}], [%7];"
        :: "r"(dst), "l"(tmap),
           "r"(0), "r"(rows.x), "r"(rows.y), "r"(rows.z), "r"(rows.w),
           "r"(mbar_addr)
        : "memory");
}

__device__ __forceinline__ void st_stream_f32(float* p, float v) {
    asm volatile("st.global.cs.f32 [%0], %1;" :: "l"(p), "f"(v) : "memory");
}

__global__ void __launch_bounds__(TPB)
dist_tma_kernel(const __grid_constant__ CUtensorMap tmap,
                const int* __restrict__ idx_i,
                const int* __restrict__ idx_j,
                float* __restrict__ out,
                int n_edges) {
    __shared__ __align__(8) unsigned long long mbar;
    __shared__ __align__(128) float smemI[SIDE_BYTES / 4];
    __shared__ __align__(128) float smemJ[SIDE_BYTES / 4];

    int t = threadIdx.x;
    unsigned base = blockIdx.x * TILE_EDGES;
    unsigned n = (unsigned)n_edges;
    uint32_t mbar_addr = smem_u32(&mbar);

    if (t == 0) {
        asm volatile("mbarrier.init.shared.b64 [%0], 1;" :: "r"(mbar_addr) : "memory");
        asm volatile("mbarrier.arrive.expect_tx.shared.b64 _, [%0], %1;"
                     :: "r"(mbar_addr), "r"((uint32_t)TX_BYTES) : "memory");
    }
    __syncthreads();

    bool full = (base + TILE_EDGES) <= n;

    // Every thread issues exactly one gather4 (256 total = TX_BYTES).
    // t < 128: i-side edges [4k, 4k+4);  t >= 128: j-side.
    {
        int k = t & 127;
        const int* src = (t < 128) ? idx_i : idx_j;
        unsigned e0 = base + 4u * k;
        int4 v;
        if (full) {
            v = *reinterpret_cast<const int4*>(src + e0);
        } else {
            v.x = (e0 + 0u < n) ? src[e0 + 0u] : 0;
            v.y = (e0 + 1u < n) ? src[e0 + 1u] : 0;
            v.z = (e0 + 2u < n) ? src[e0 + 2u] : 0;
            v.w = (e0 + 3u < n) ? src[e0 + 3u] : 0;
        }
        uint32_t dst = ((t < 128) ? smem_u32(smemI) : smem_u32(smemJ))
                       + (uint32_t)k * BLOCK_BYTES;
        tma_gather4(dst, &tmap, v, mbar_addr);
    }

    // Single-waiter: only thread 0 polls the mbarrier; everyone else sleeps
    // at the barrier (no chip-wide spin traffic).
    if (t == 0) {
        uint32_t done = 0;
        do {
            asm volatile(
                "{ .reg .pred p; mbarrier.try_wait.parity.acquire.cta.shared::cta.b64 "
                "p, [%1], %2, 0x989680; selp.b32 %0, 1, 0, p; }"
                : "=r"(done) : "r"(mbar_addr), "r"(0u) : "memory");
        } while (!done);
    }
    __syncthreads();

    // Gather4 block g holds rows for edges [4g, 4g+4) contiguously:
    // edge e's row is at byte offset e*32 → float offset e*8.
    if (full) {
        #pragma unroll
        for (int s = 0; s < 2; ++s) {
            int e = t + s * TPB;
            float4 a = *reinterpret_cast<const float4*>(&smemI[e * 8]);
            float4 b = *reinterpret_cast<const float4*>(&smemJ[e * 8]);
            float dx = a.x - b.x;
            float dy = a.y - b.y;
            float dz = a.z - b.z;
            st_stream_f32(out + base + e, sqrtf(dx * dx + dy * dy + dz * dz));
        }
    } else {
        #pragma unroll
        for (int s = 0; s < 2; ++s) {
            int e = t + s * TPB;
            unsigned ge = base + (unsigned)e;
            if (ge < n) {
                float4 a = *reinterpret_cast<const float4*>(&smemI[e * 8]);
                float4 b = *reinterpret_cast<const float4*>(&smemJ[e * 8]);
                float dx = a.x - b.x;
                float dy = a.y - b.y;
                float dz = a.z - b.z;
                st_stream_f32(out + ge, sqrtf(dx * dx + dy * dy + dz * dz));
            }
        }
    }
}

// ───────────────────────── fallback LDG kernel (proven ~55us) ─────────────────────────
__device__ __forceinline__ int4 ld_stream_int4(const int4* p) {
    int4 v;
    asm volatile("ld.global.nc.L1::no_allocate.v4.b32 {%0,%1,%2,%3}, [%4];"
                 : "=r"(v.x), "=r"(v.y), "=r"(v.z), "=r"(v.w) : "l"(p));
    return v;
}
__device__ __forceinline__ void st_stream_float4(float4* p, float4 v) {
    asm volatile("st.global.cs.v4.f32 [%0], {%1,%2,%3,%4};"
                 :: "l"(p), "f"(v.x), "f"(v.y), "f"(v.z), "f"(v.w) : "memory");
}
__device__ __forceinline__ float edge_dist(int i, int j) {
    float4 a = *reinterpret_cast<const float4*>(g_R8[i]);
    float4 b = *reinterpret_cast<const float4*>(g_R8[j]);
    float dx = a.x - b.x, dy = a.y - b.y, dz = a.z - b.z;
    return sqrtf(dx * dx + dy * dy + dz * dz);
}
__global__ void dist_kernel(const int* __restrict__ idx_i,
                            const int* __restrict__ idx_j,
                            float* __restrict__ out, int n_edges) {
    unsigned t = blockIdx.x * blockDim.x + threadIdx.x;
    unsigned base = t * 8u;
    if (base + 8u <= (unsigned)n_edges) {
        const int4* pi = reinterpret_cast<const int4*>(idx_i + base);
        const int4* pj = reinterpret_cast<const int4*>(idx_j + base);
        int4 i0 = ld_stream_int4(pi + 0);
        int4 i1 = ld_stream_int4(pi + 1);
        int4 j0 = ld_stream_int4(pj + 0);
        int4 j1 = ld_stream_int4(pj + 1);
        float4 r0, r1;
        r0.x = edge_dist(i0.x, j0.x); r0.y = edge_dist(i0.y, j0.y);
        r0.z = edge_dist(i0.z, j0.z); r0.w = edge_dist(i0.w, j0.w);
        r1.x = edge_dist(i1.x, j1.x); r1.y = edge_dist(i1.y, j1.y);
        r1.z = edge_dist(i1.z, j1.z); r1.w = edge_dist(i1.w, j1.w);
        st_stream_float4(reinterpret_cast<float4*>(out + base) + 0, r0);
        st_stream_float4(reinterpret_cast<float4*>(out + base) + 1, r1);
    } else if (base < (unsigned)n_edges) {
        for (unsigned e = base; e < (unsigned)n_edges; ++e)
            out[e] = edge_dist(idx_i[e], idx_j[e]);
    }
}

// ───────────────────────── host ─────────────────────────
typedef CUresult (*PFN_encodeTiled)(
    CUtensorMap*, CUtensorMapDataType, cuuint32_t, void*,
    const cuuint64_t*, const cuuint64_t*, const cuuint32_t*, const cuuint32_t*,
    CUtensorMapInterleave, CUtensorMapSwizzle, CUtensorMapL2promotion,
    CUtensorMapFloatOOBfill);

extern "C" void kernel_launch(void* const* d_in, const int* in_sizes, int n_in,
                              void* d_out, int out_size) {
    const float* R   = (const float*)d_in[0];
    const int* idx_i = (const int*)d_in[1];
    const int* idx_j = (const int*)d_in[2];
    float* out       = (float*)d_out;

    int n_atoms = in_sizes[0] / 3;
    int n_edges = in_sizes[1];

    {
        int threads = 256;
        int blocks = (n_atoms + threads - 1) / threads;
        pad_R_kernel<<<blocks, threads>>>(R, n_atoms);
    }

    // Build gather tensormap host-side. gather4 supplies the 4 row coords in
    // the instruction, so the box is {row_width=8 f32, 1}. If encode fails,
    // fall back to the proven LDG kernel (bounded downside).
    bool use_tma = false;
    CUtensorMap tmap;
    void* fn = nullptr;
    cudaDriverEntryPointQueryResult qres;
    if (cudaGetDriverEntryPoint("cuTensorMapEncodeTiled", &fn,
                                cudaEnableDefault, &qres) == cudaSuccess && fn) {
        void* dR8 = nullptr;
        if (cudaGetSymbolAddress(&dR8, g_R8) == cudaSuccess && dR8) {
            cuuint64_t gdims[2]   = {8, (cuuint64_t)MAX_ATOMS};  // 8 f32 per row
            cuuint64_t gstride[1] = {32};                        // 32B row stride
            cuuint32_t estr[2]    = {1, 1};
            cuuint32_t box[2]     = {8, 1};                      // gather4: height 1
            PFN_encodeTiled enc = (PFN_encodeTiled)fn;
            if (enc(&tmap, CU_TENSOR_MAP_DATA_TYPE_FLOAT32, 2, dR8,
                    gdims, gstride, box, estr,
                    CU_TENSOR_MAP_INTERLEAVE_NONE, CU_TENSOR_MAP_SWIZZLE_NONE,
                    CU_TENSOR_MAP_L2_PROMOTION_NONE,
                    CU_TENSOR_MAP_FLOAT_OOB_FILL_NONE) == CUDA_SUCCESS) {
                use_tma = true;
            }
        }
    }

    if (use_tma) {
        int blocks = (n_edges + TILE_EDGES - 1) / TILE_EDGES;
        dist_tma_kernel<<<blocks, TPB>>>(tmap, idx_i, idx_j, out, n_edges);
    } else {
        int threads = 256;
        int epb = threads * 8;
        int blocks = (n_edges + epb - 1) / epb;
        dist_kernel<<<blocks, threads>>>(idx_i, idx_j, out, n_edges);
    }
}